// round 1
// baseline (speedup 1.0000x reference)
#include <cuda_runtime.h>
#include <math.h>

#define B_ 4
#define N_ 1024
#define D_ 768
#define H_ 12
#define HD_ 64
#define ND3_ 2304

// Scratch (device globals — no allocation allowed)
__device__ float g_q[B_ * H_ * N_ * HD_];
__device__ float g_k[B_ * H_ * N_ * HD_];
__device__ float g_v[B_ * H_ * N_ * HD_];
__device__ float g_ctx[B_ * N_ * D_];

// ---------------------------------------------------------------------------
// Kernel 1: QKV GEMM.  C[m,n] = sum_k X[m,k] * W[k,n],  M=4096, N=2304, K=768.
// Epilogue scatters into g_q/g_k/g_v with layout [B,H,N,hd].
// 64x64 block tile, BK=16, 256 threads, 4x4 micro-tile, register prefetch.
// ---------------------------------------------------------------------------
__global__ __launch_bounds__(256) void qkv_gemm_kernel(
    const float* __restrict__ X, const float* __restrict__ W) {
    __shared__ float As[16][68];  // transposed: As[k][m]
    __shared__ float Bs[16][68];  // Bs[k][n]

    const int m0 = blockIdx.y * 64;
    const int n0 = blockIdx.x * 64;
    const int tid = threadIdx.x;
    const int ty = tid >> 4, tx = tid & 15;

    const int lrow = tid >> 2, lkq = tid & 3;   // A loader: row, k-quad
    const int lkr = tid >> 4, lnc = tid & 15;   // B loader: k-row, n-quad

    const float* xp = X + (size_t)(m0 + lrow) * D_ + lkq * 4;
    const float* wp = W + (size_t)lkr * ND3_ + n0 + lnc * 4;

    float4 pa = *(const float4*)xp;
    float4 pb = *(const float4*)wp;

    float acc[4][4];
#pragma unroll
    for (int i = 0; i < 4; i++)
#pragma unroll
        for (int j = 0; j < 4; j++) acc[i][j] = 0.0f;

    for (int kt = 0; kt < 48; ++kt) {
        As[lkq * 4 + 0][lrow] = pa.x;
        As[lkq * 4 + 1][lrow] = pa.y;
        As[lkq * 4 + 2][lrow] = pa.z;
        As[lkq * 4 + 3][lrow] = pa.w;
        *(float4*)&Bs[lkr][lnc * 4] = pb;
        __syncthreads();
        if (kt < 47) {
            pa = *(const float4*)(xp + (kt + 1) * 16);
            pb = *(const float4*)(wp + (size_t)(kt + 1) * 16 * ND3_);
        }
#pragma unroll
        for (int k = 0; k < 16; ++k) {
            float4 a4 = *(const float4*)&As[k][ty * 4];
            float4 b4 = *(const float4*)&Bs[k][tx * 4];
            acc[0][0] += a4.x * b4.x; acc[0][1] += a4.x * b4.y;
            acc[0][2] += a4.x * b4.z; acc[0][3] += a4.x * b4.w;
            acc[1][0] += a4.y * b4.x; acc[1][1] += a4.y * b4.y;
            acc[1][2] += a4.y * b4.z; acc[1][3] += a4.y * b4.w;
            acc[2][0] += a4.z * b4.x; acc[2][1] += a4.z * b4.y;
            acc[2][2] += a4.z * b4.z; acc[2][3] += a4.z * b4.w;
            acc[3][0] += a4.w * b4.x; acc[3][1] += a4.w * b4.y;
            acc[3][2] += a4.w * b4.z; acc[3][3] += a4.w * b4.w;
        }
        __syncthreads();
    }

    // Scatter: n-tile (64 wide) covers exactly one (which, head) pair.
    const int which = n0 / D_;               // 0=q,1=k,2=v
    const int h = (n0 - which * D_) >> 6;    // head
    float* dst = (which == 0) ? g_q : (which == 1) ? g_k : g_v;
#pragma unroll
    for (int i = 0; i < 4; ++i) {
        int m = m0 + ty * 4 + i;
        int b = m >> 10, r = m & 1023;
        float4 o = make_float4(acc[i][0], acc[i][1], acc[i][2], acc[i][3]);
        *(float4*)&dst[(((size_t)(b * H_ + h) * N_ + r) << 6) + tx * 4] = o;
    }
}

// ---------------------------------------------------------------------------
// Kernel 2: flash attention with fused bucketed rel-pos bias + elevation bias.
// Grid: (16 i-tiles, H, B), 256 threads. Dynamic smem.
// ---------------------------------------------------------------------------
#define ATTN_SMEM_FLOATS (3 * 64 * 68 + 1024 + 256 + 64 + 64 + 64)
#define ATTN_SMEM_BYTES (ATTN_SMEM_FLOATS * 4)

__global__ __launch_bounds__(256) void attn_kernel(
    const float* __restrict__ coords, const float* __restrict__ elev,
    const float* __restrict__ bias_table, const float* __restrict__ alphap) {
    extern __shared__ float smf[];
    float(*qs)[68] = (float(*)[68])smf;                  // [64][68] q natural
    float(*kps)[68] = (float(*)[68])(smf + 64 * 68);     // K transposed / P
    float(*vs)[68] = (float(*)[68])(smf + 2 * 64 * 68);  // V natural
    float* tbl = smf + 3 * 64 * 68;                      // per-head bias slice [1024]
    int* lut = (int*)(tbl + 1024);                       // bucket LUT [255]
    int* cjx = lut + 256;
    int* cjy = cjx + 64;
    float* ejs = (float*)(cjy + 64);

    const int i0 = blockIdx.x * 64;
    const int h = blockIdx.y;
    const int b = blockIdx.z;
    const int tid = threadIdx.x;
    const int ty = tid >> 4, tx = tid & 15;

    // per-head bias table slice
    for (int idx = tid; idx < 1024; idx += 256) tbl[idx] = bias_table[idx * H_ + h];

    // bucket LUT: rel in [-127,127]. Double-precision log matches XLA fp32
    // truncation (boundaries n=16/32/64 are exactly integral in both).
    if (tid < 255) {
        int rel = tid - 127;
        int ret = (rel > 0) ? 16 : 0;
        int n = (rel < 0) ? -rel : rel;
        int bb;
        if (n < 8) bb = n;
        else {
            int vi = (int)(log((double)n * 0.125) / log(16.0) * 8.0 + 1e-9);
            bb = 8 + vi;
            if (bb > 15) bb = 15;
        }
        lut[tid] = ret + bb;
    }

    // q tile
    const float* qbase = g_q + (((size_t)(b * H_ + h) * N_ + i0) << 6);
#pragma unroll
    for (int p = 0; p < 4; ++p) {
        int idx = tid + p * 256;
        int r = idx >> 4, dq = idx & 15;
        *(float4*)&qs[r][dq * 4] = *(const float4*)(qbase + r * 64 + dq * 4);
    }

    // per-row registers
    int cix[4], ciy[4];
    float eir[4];
#pragma unroll
    for (int i = 0; i < 4; ++i) {
        int g = b * N_ + i0 + ty * 4 + i;
        cix[i] = (int)(coords[g * 2 + 0] * 128.0f);
        ciy[i] = (int)(coords[g * 2 + 1] * 128.0f);
        eir[i] = elev[g] * (1.0f / 1000.0f);
    }
    const float alpha = *alphap;

    float oacc[4][4];
    float mrow[4], lrow[4];
#pragma unroll
    for (int i = 0; i < 4; ++i) {
        mrow[i] = -1e30f;
        lrow[i] = 0.0f;
#pragma unroll
        for (int j = 0; j < 4; ++j) oacc[i][j] = 0.0f;
    }

    const float* kbase0 = g_k + (((size_t)(b * H_ + h) * N_) << 6);
    const float* vbase0 = g_v + (((size_t)(b * H_ + h) * N_) << 6);

    for (int jt = 0; jt < 16; ++jt) {
        const int j0 = jt * 64;
        __syncthreads();  // protect kps/vs from previous iteration's readers
        const float* kbase = kbase0 + ((size_t)j0 << 6);
        const float* vbase = vbase0 + ((size_t)j0 << 6);
#pragma unroll
        for (int p = 0; p < 4; ++p) {
            int idx = tid + p * 256;
            int r = idx >> 4, dq = idx & 15;
            float4 kv = *(const float4*)(kbase + r * 64 + dq * 4);
            kps[dq * 4 + 0][r] = kv.x;
            kps[dq * 4 + 1][r] = kv.y;
            kps[dq * 4 + 2][r] = kv.z;
            kps[dq * 4 + 3][r] = kv.w;
            *(float4*)&vs[r][dq * 4] = *(const float4*)(vbase + r * 64 + dq * 4);
        }
        if (tid < 64) {
            int g = b * N_ + j0 + tid;
            cjx[tid] = (int)(coords[g * 2 + 0] * 128.0f);
            cjy[tid] = (int)(coords[g * 2 + 1] * 128.0f);
            ejs[tid] = elev[g] * (1.0f / 1000.0f);
        }
        __syncthreads();

        // S = Q K^T
        float s[4][4];
#pragma unroll
        for (int i = 0; i < 4; i++)
#pragma unroll
            for (int j = 0; j < 4; j++) s[i][j] = 0.0f;
#pragma unroll 16
        for (int d = 0; d < 64; ++d) {
            float4 b4 = *(const float4*)&kps[d][tx * 4];
#pragma unroll
            for (int i = 0; i < 4; ++i) {
                float a = qs[ty * 4 + i][d];
                s[i][0] += a * b4.x;
                s[i][1] += a * b4.y;
                s[i][2] += a * b4.z;
                s[i][3] += a * b4.w;
            }
        }

        // biases
#pragma unroll
        for (int i = 0; i < 4; ++i) {
#pragma unroll
            for (int j = 0; j < 4; ++j) {
                int jj = tx * 4 + j;
                float sc = s[i][j] * 0.125f;
                int bx = lut[cix[i] - cjx[jj] + 127];
                int by = lut[ciy[i] - cjy[jj] + 127];
                sc += tbl[(bx << 5) + by];
                float ed = ejs[jj] - eir[i];
                float eb = -alpha * fmaxf(ed, 0.0f);
                sc += fminf(fmaxf(eb, -10.0f), 0.0f);
                s[i][j] = sc;
            }
        }

        // online softmax (row groups = 16 lanes sharing ty)
#pragma unroll
        for (int i = 0; i < 4; ++i) {
            float tm = fmaxf(fmaxf(s[i][0], s[i][1]), fmaxf(s[i][2], s[i][3]));
            tm = fmaxf(tm, __shfl_xor_sync(0xffffffff, tm, 1));
            tm = fmaxf(tm, __shfl_xor_sync(0xffffffff, tm, 2));
            tm = fmaxf(tm, __shfl_xor_sync(0xffffffff, tm, 4));
            tm = fmaxf(tm, __shfl_xor_sync(0xffffffff, tm, 8));
            float mnew = fmaxf(mrow[i], tm);
            float corr = __expf(mrow[i] - mnew);
            mrow[i] = mnew;
            float psum = 0.0f;
#pragma unroll
            for (int j = 0; j < 4; ++j) {
                float pv = __expf(s[i][j] - mnew);
                s[i][j] = pv;
                psum += pv;
            }
            lrow[i] = lrow[i] * corr + psum;
            oacc[i][0] *= corr;
            oacc[i][1] *= corr;
            oacc[i][2] *= corr;
            oacc[i][3] *= corr;
        }

        __syncthreads();  // everyone done reading kps (K) before P overwrite
#pragma unroll
        for (int i = 0; i < 4; ++i)
            *(float4*)&kps[ty * 4 + i][tx * 4] =
                make_float4(s[i][0], s[i][1], s[i][2], s[i][3]);
        __syncthreads();

        // O += P V
#pragma unroll 16
        for (int jj = 0; jj < 64; ++jj) {
            float4 v4 = *(const float4*)&vs[jj][tx * 4];
#pragma unroll
            for (int i = 0; i < 4; ++i) {
                float pv = kps[ty * 4 + i][jj];
                oacc[i][0] += pv * v4.x;
                oacc[i][1] += pv * v4.y;
                oacc[i][2] += pv * v4.z;
                oacc[i][3] += pv * v4.w;
            }
        }
    }

    // finalize
#pragma unroll
    for (int i = 0; i < 4; ++i) {
        float l = lrow[i];
        l += __shfl_xor_sync(0xffffffff, l, 1);
        l += __shfl_xor_sync(0xffffffff, l, 2);
        l += __shfl_xor_sync(0xffffffff, l, 4);
        l += __shfl_xor_sync(0xffffffff, l, 8);
        float inv = 1.0f / l;
        int row = i0 + ty * 4 + i;
        float4 o = make_float4(oacc[i][0] * inv, oacc[i][1] * inv,
                               oacc[i][2] * inv, oacc[i][3] * inv);
        *(float4*)&g_ctx[((size_t)(b * N_ + row)) * D_ + h * 64 + tx * 4] = o;
    }
}

// ---------------------------------------------------------------------------
// Kernel 3: output projection.  out = ctx @ W_proj + b_proj.  M=4096,N=768,K=768
// ---------------------------------------------------------------------------
__global__ __launch_bounds__(256) void proj_gemm_kernel(
    const float* __restrict__ W, const float* __restrict__ bias,
    float* __restrict__ out) {
    __shared__ float As[16][68];
    __shared__ float Bs[16][68];

    const int m0 = blockIdx.y * 64;
    const int n0 = blockIdx.x * 64;
    const int tid = threadIdx.x;
    const int ty = tid >> 4, tx = tid & 15;

    const int lrow = tid >> 2, lkq = tid & 3;
    const int lkr = tid >> 4, lnc = tid & 15;

    const float* xp = g_ctx + (size_t)(m0 + lrow) * D_ + lkq * 4;
    const float* wp = W + (size_t)lkr * D_ + n0 + lnc * 4;

    float4 pa = *(const float4*)xp;
    float4 pb = *(const float4*)wp;

    float acc[4][4];
#pragma unroll
    for (int i = 0; i < 4; i++)
#pragma unroll
        for (int j = 0; j < 4; j++) acc[i][j] = 0.0f;

    for (int kt = 0; kt < 48; ++kt) {
        As[lkq * 4 + 0][lrow] = pa.x;
        As[lkq * 4 + 1][lrow] = pa.y;
        As[lkq * 4 + 2][lrow] = pa.z;
        As[lkq * 4 + 3][lrow] = pa.w;
        *(float4*)&Bs[lkr][lnc * 4] = pb;
        __syncthreads();
        if (kt < 47) {
            pa = *(const float4*)(xp + (kt + 1) * 16);
            pb = *(const float4*)(wp + (size_t)(kt + 1) * 16 * D_);
        }
#pragma unroll
        for (int k = 0; k < 16; ++k) {
            float4 a4 = *(const float4*)&As[k][ty * 4];
            float4 b4 = *(const float4*)&Bs[k][tx * 4];
            acc[0][0] += a4.x * b4.x; acc[0][1] += a4.x * b4.y;
            acc[0][2] += a4.x * b4.z; acc[0][3] += a4.x * b4.w;
            acc[1][0] += a4.y * b4.x; acc[1][1] += a4.y * b4.y;
            acc[1][2] += a4.y * b4.z; acc[1][3] += a4.y * b4.w;
            acc[2][0] += a4.z * b4.x; acc[2][1] += a4.z * b4.y;
            acc[2][2] += a4.z * b4.z; acc[2][3] += a4.z * b4.w;
            acc[3][0] += a4.w * b4.x; acc[3][1] += a4.w * b4.y;
            acc[3][2] += a4.w * b4.z; acc[3][3] += a4.w * b4.w;
        }
        __syncthreads();
    }

    float4 bb = *(const float4*)&bias[n0 + tx * 4];
#pragma unroll
    for (int i = 0; i < 4; ++i) {
        int m = m0 + ty * 4 + i;
        float4 o = make_float4(acc[i][0] + bb.x, acc[i][1] + bb.y,
                               acc[i][2] + bb.z, acc[i][3] + bb.w);
        *(float4*)&out[(size_t)m * D_ + n0 + tx * 4] = o;
    }
}

// ---------------------------------------------------------------------------
extern "C" void kernel_launch(void* const* d_in, const int* in_sizes, int n_in,
                              void* d_out, int out_size) {
    const float* x = (const float*)d_in[0];
    const float* coords = (const float*)d_in[1];
    const float* elev = (const float*)d_in[2];
    const float* W_qkv = (const float*)d_in[3];
    const float* W_proj = (const float*)d_in[4];
    const float* b_proj = (const float*)d_in[5];
    const float* bias_table = (const float*)d_in[6];
    const float* alpha = (const float*)d_in[7];
    float* out = (float*)d_out;

    cudaFuncSetAttribute(attn_kernel, cudaFuncAttributeMaxDynamicSharedMemorySize,
                         ATTN_SMEM_BYTES);

    qkv_gemm_kernel<<<dim3(ND3_ / 64, (B_ * N_) / 64), 256>>>(x, W_qkv);
    attn_kernel<<<dim3(N_ / 64, H_, B_), 256, ATTN_SMEM_BYTES>>>(coords, elev,
                                                                 bias_table, alpha);
    proj_gemm_kernel<<<dim3(D_ / 64, (B_ * N_) / 64), 256>>>(W_proj, b_proj, out);
}